// round 10
// baseline (speedup 1.0000x reference)
#include <cuda_runtime.h>
#include <cstdint>

#define BB 4
#define NNODES 2048
#define DD 256
#define HH 8
#define HDIM 32
#define EE 65536
#define MASK_WORDS (NNODES / 32)   /* 64 */
#define MAXDEG 128
#define WPB 8                      /* warps per block in attn */

// ---------------- device scratch (no allocation allowed) ----------------
__device__ float g_Q[BB * NNODES * DD];
__device__ float g_K[BB * NNODES * DD];
__device__ float g_V[BB * NNODES * DD];
__device__ float g_att[BB * NNODES * DD];
__device__ unsigned int g_mask[NNODES * MASK_WORDS];

// ---------------- adjacency mask ----------------
__global__ void build_mask_kernel(const int* __restrict__ edges) {
    int idx = blockIdx.x * blockDim.x + threadIdx.x;
    if (idx < EE) {
        int s = edges[idx];
        int d = edges[EE + idx];
        atomicOr(&g_mask[s * MASK_WORDS + (d >> 5)], 1u << (d & 31));
        atomicOr(&g_mask[d * MASK_WORDS + (s >> 5)], 1u << (s & 31));
    } else if (idx < EE + NNODES) {
        int i = idx - EE;
        atomicOr(&g_mask[i * MASK_WORDS + (i >> 5)], 1u << (i & 31));
    }
}

// ---------------- SGEMM: C[M,256] = A[M,256] @ W[256,256]^T + bias ----------------
// 128 threads, BM=64, BN=128, BK=16, 8x8 per-thread micro-tile.
// Smaller M-tile -> 2x the blocks -> 3-4 concurrent CTAs/SM for latency hiding.
__device__ __forceinline__ void sgemm_body(const float* __restrict__ A,
                                           const float* __restrict__ W,
                                           const float* __restrict__ bias,
                                           float* __restrict__ C) {
    __shared__ float As[16][64];
    __shared__ float Ws[16][128];

    const int tid = threadIdx.x;          // 0..127
    const int m0 = blockIdx.x * 64;
    const int n0 = blockIdx.y * 128;
    const int tx = tid & 15;              // 0..15 (N direction)
    const int ty = tid >> 4;              // 0..7  (M direction)
    const int lrA = tid >> 1;             // A load row 0..63
    const int lhA = (tid & 1) * 8;        // A k-half offset 0 or 8

    float acc[8][8];
#pragma unroll
    for (int i = 0; i < 8; i++)
#pragma unroll
        for (int j = 0; j < 8; j++) acc[i][j] = 0.f;

    const float* Ap = A + (size_t)(m0 + lrA) * 256 + lhA;
    const float* Wp = W + (size_t)(n0 + tid) * 256;

    for (int k0 = 0; k0 < 256; k0 += 16) {
        float4 a0 = reinterpret_cast<const float4*>(Ap + k0)[0];
        float4 a1 = reinterpret_cast<const float4*>(Ap + k0)[1];
        float4 w0 = reinterpret_cast<const float4*>(Wp + k0)[0];
        float4 w1 = reinterpret_cast<const float4*>(Wp + k0)[1];
        float4 w2 = reinterpret_cast<const float4*>(Wp + k0)[2];
        float4 w3 = reinterpret_cast<const float4*>(Wp + k0)[3];

        __syncthreads();   // previous iteration's readers done
        As[lhA + 0][lrA] = a0.x; As[lhA + 1][lrA] = a0.y; As[lhA + 2][lrA] = a0.z; As[lhA + 3][lrA] = a0.w;
        As[lhA + 4][lrA] = a1.x; As[lhA + 5][lrA] = a1.y; As[lhA + 6][lrA] = a1.z; As[lhA + 7][lrA] = a1.w;
        Ws[0][tid] = w0.x;  Ws[1][tid] = w0.y;  Ws[2][tid] = w0.z;  Ws[3][tid] = w0.w;
        Ws[4][tid] = w1.x;  Ws[5][tid] = w1.y;  Ws[6][tid] = w1.z;  Ws[7][tid] = w1.w;
        Ws[8][tid] = w2.x;  Ws[9][tid] = w2.y;  Ws[10][tid] = w2.z; Ws[11][tid] = w2.w;
        Ws[12][tid] = w3.x; Ws[13][tid] = w3.y; Ws[14][tid] = w3.z; Ws[15][tid] = w3.w;
        __syncthreads();

#pragma unroll
        for (int k = 0; k < 16; k++) {
            float4 aA = *reinterpret_cast<const float4*>(&As[k][ty * 8]);
            float4 aB = *reinterpret_cast<const float4*>(&As[k][ty * 8 + 4]);
            float4 bA = *reinterpret_cast<const float4*>(&Ws[k][tx * 8]);
            float4 bB = *reinterpret_cast<const float4*>(&Ws[k][tx * 8 + 4]);
            float a[8] = {aA.x, aA.y, aA.z, aA.w, aB.x, aB.y, aB.z, aB.w};
            float w[8] = {bA.x, bA.y, bA.z, bA.w, bB.x, bB.y, bB.z, bB.w};
#pragma unroll
            for (int i = 0; i < 8; i++)
#pragma unroll
                for (int j = 0; j < 8; j++) acc[i][j] += a[i] * w[j];
        }
    }

    float bs[8];
#pragma unroll
    for (int j = 0; j < 8; j++) bs[j] = bias[n0 + tx * 8 + j];

#pragma unroll
    for (int i = 0; i < 8; i++) {
        float* Cr = C + (size_t)(m0 + ty * 8 + i) * 256 + n0 + tx * 8;
        float4 o0, o1;
        o0.x = acc[i][0] + bs[0]; o0.y = acc[i][1] + bs[1];
        o0.z = acc[i][2] + bs[2]; o0.w = acc[i][3] + bs[3];
        o1.x = acc[i][4] + bs[4]; o1.y = acc[i][5] + bs[5];
        o1.z = acc[i][6] + bs[6]; o1.w = acc[i][7] + bs[7];
        reinterpret_cast<float4*>(Cr)[0] = o0;
        reinterpret_cast<float4*>(Cr)[1] = o1;
    }
}

__global__ void __launch_bounds__(128) qkv_kernel(const float* __restrict__ x,
                                                  const float* __restrict__ Wq, const float* __restrict__ bq,
                                                  const float* __restrict__ Wk, const float* __restrict__ bk,
                                                  const float* __restrict__ Wv, const float* __restrict__ bv) {
    const float* W; const float* bb; float* C;
    if (blockIdx.z == 0)      { W = Wq; bb = bq; C = g_Q; }
    else if (blockIdx.z == 1) { W = Wk; bb = bk; C = g_K; }
    else                      { W = Wv; bb = bv; C = g_V; }
    sgemm_body(x, W, bb, C);
}

__global__ void __launch_bounds__(128) oproj_kernel(const float* __restrict__ Wo,
                                                    const float* __restrict__ bo,
                                                    float* __restrict__ out) {
    sgemm_body(g_att, Wo, bo, out);
}

// ---------------- sparse masked attention: single pass, online softmax ----------------
// One warp per (b,i). Lane layout: h = lane>>2 (head), s = lane&3.
// Each 2-neighbor iteration loads K rows AND V rows (8 LDG.128 in flight) and
// folds them into a running (m, l, acc) online-softmax state. All 4 lanes of a
// head group hold identical (m, l) so no cross-lane softmax reductions remain.
// Raw scores are kept in smem; attn_mean is recomputed at scatter time.
__global__ void __launch_bounds__(32 * WPB) attn_kernel(const float* __restrict__ tptr,
                                                        float* __restrict__ attn_out) {
    __shared__ unsigned short s_idx[WPB][MAXDEG];
    __shared__ float s_s[WPB][8][MAXDEG + 1];   // raw scaled scores, +1 pad
    __shared__ float s_ml[WPB][8][2];           // per-head {max, 1/l}

    const int warp = threadIdx.x >> 5;
    const int lane = threadIdx.x & 31;
    const int flat = blockIdx.x * WPB + warp;        // 0 .. B*N-1
    const int b = flat >> 11;
    const int i = flat & (NNODES - 1);
    const float invT = 1.0f / (*tptr);

    // --- enumerate neighbors from bitmask row i ---
    unsigned int w0 = g_mask[i * MASK_WORDS + lane];
    unsigned int w1 = g_mask[i * MASK_WORDS + 32 + lane];
    int c0 = __popc(w0), c1 = __popc(w1);

    int incl0 = c0;
#pragma unroll
    for (int d = 1; d < 32; d <<= 1) {
        int t = __shfl_up_sync(0xffffffffu, incl0, d);
        if (lane >= d) incl0 += t;
    }
    int tot0 = __shfl_sync(0xffffffffu, incl0, 31);
    int off0 = incl0 - c0;

    int incl1 = c1;
#pragma unroll
    for (int d = 1; d < 32; d <<= 1) {
        int t = __shfl_up_sync(0xffffffffu, incl1, d);
        if (lane >= d) incl1 += t;
    }
    int tot1 = __shfl_sync(0xffffffffu, incl1, 31);
    int off1 = tot0 + incl1 - c1;

    int deg = tot0 + tot1;
    if (deg > MAXDEG) deg = MAXDEG;   // statistically unreachable (Poisson(64) tail)

    {
        int o = off0, base = lane * 32;
        while (w0) {
            int p = __ffs(w0) - 1; w0 &= w0 - 1;
            if (o < MAXDEG) s_idx[warp][o] = (unsigned short)(base + p);
            o++;
        }
        o = off1; base = 1024 + lane * 32;
        while (w1) {
            int p = __ffs(w1) - 1; w1 &= w1 - 1;
            if (o < MAXDEG) s_idx[warp][o] = (unsigned short)(base + p);
            o++;
        }
    }
    __syncwarp();

    const int h = lane >> 2;          // head owned by this 4-lane group
    const int s = lane & 3;
    const size_t rowbase = (size_t)(b * NNODES + i) * DD;
    const float* __restrict__ Kb = g_K + (size_t)b * NNODES * DD;
    const float* __restrict__ Vb = g_V + (size_t)b * NNODES * DD;

    const float* Qrow = g_Q + rowbase + h * 32 + s * 8;
    const float4 qa = reinterpret_cast<const float4*>(Qrow)[0];
    const float4 qb = reinterpret_cast<const float4*>(Qrow)[1];

    float m = -1e30f, l = 0.f;
    float4 acca = {0.f, 0.f, 0.f, 0.f};
    float4 accb = {0.f, 0.f, 0.f, 0.f};

    for (int nb = 0; nb < deg; nb += 2) {
        const bool has1 = (nb + 1) < deg;
        const int j0 = s_idx[warp][nb];
        const int j1 = s_idx[warp][has1 ? nb + 1 : nb];

        const float* K0 = Kb + (size_t)j0 * DD + h * 32 + s * 8;
        const float* K1 = Kb + (size_t)j1 * DD + h * 32 + s * 8;
        const float* V0 = Vb + (size_t)j0 * DD + lane * 8;
        const float* V1 = Vb + (size_t)j1 * DD + lane * 8;
        float4 ka0 = reinterpret_cast<const float4*>(K0)[0];
        float4 kb0 = reinterpret_cast<const float4*>(K0)[1];
        float4 ka1 = reinterpret_cast<const float4*>(K1)[0];
        float4 kb1 = reinterpret_cast<const float4*>(K1)[1];
        float4 va0 = reinterpret_cast<const float4*>(V0)[0];
        float4 vb0 = reinterpret_cast<const float4*>(V0)[1];
        float4 va1 = reinterpret_cast<const float4*>(V1)[0];
        float4 vb1 = reinterpret_cast<const float4*>(V1)[1];

        float d0 = qa.x * ka0.x + qa.y * ka0.y + qa.z * ka0.z + qa.w * ka0.w
                 + qb.x * kb0.x + qb.y * kb0.y + qb.z * kb0.z + qb.w * kb0.w;
        float d1 = qa.x * ka1.x + qa.y * ka1.y + qa.z * ka1.z + qa.w * ka1.w
                 + qb.x * kb1.x + qb.y * kb1.y + qb.z * kb1.z + qb.w * kb1.w;
        d0 += __shfl_xor_sync(0xffffffffu, d0, 1);
        d0 += __shfl_xor_sync(0xffffffffu, d0, 2);
        d1 += __shfl_xor_sync(0xffffffffu, d1, 1);
        d1 += __shfl_xor_sync(0xffffffffu, d1, 2);

        const float s0 = d0 * invT;
        const float s1 = has1 ? d1 * invT : -1e30f;
        if (s == 0) {
            s_s[warp][h][nb] = s0;
            if (has1) s_s[warp][h][nb + 1] = s1;
        }

        const float mn = fmaxf(m, fmaxf(s0, s1));
        const float c  = __expf(m - mn);
        const float e0 = __expf(s0 - mn);
        const float e1 = __expf(s1 - mn);
        l = l * c + e0 + e1;
        acca.x = acca.x * c + e0 * va0.x + e1 * va1.x;
        acca.y = acca.y * c + e0 * va0.y + e1 * va1.y;
        acca.z = acca.z * c + e0 * va0.z + e1 * va1.z;
        acca.w = acca.w * c + e0 * va0.w + e1 * va1.w;
        accb.x = accb.x * c + e0 * vb0.x + e1 * vb1.x;
        accb.y = accb.y * c + e0 * vb0.y + e1 * vb1.y;
        accb.z = accb.z * c + e0 * vb0.z + e1 * vb1.z;
        accb.w = accb.w * c + e0 * vb0.w + e1 * vb1.w;
        m = mn;
    }

    const float invl = 1.0f / l;
    if (s == 0) {
        s_ml[warp][h][0] = m;
        s_ml[warp][h][1] = invl;
    }

    // --- attended output (normalize) ---
    acca.x *= invl; acca.y *= invl; acca.z *= invl; acca.w *= invl;
    accb.x *= invl; accb.y *= invl; accb.z *= invl; accb.w *= invl;
    float* Ao = g_att + rowbase + lane * 8;
    reinterpret_cast<float4*>(Ao)[0] = acca;
    reinterpret_cast<float4*>(Ao)[1] = accb;

    __syncwarp();

    // --- attn_mean sparse scatter: lanes parallel over neighbors ---
    float mh[8], ih[8];
#pragma unroll
    for (int hh = 0; hh < 8; hh++) {
        mh[hh] = s_ml[warp][hh][0];
        ih[hh] = s_ml[warp][hh][1];
    }
    float* arow = attn_out + ((size_t)b * NNODES + i) * NNODES;
    for (int n = lane; n < deg; n += 32) {
        float ps = 0.f;
#pragma unroll
        for (int hh = 0; hh < 8; hh++)
            ps += __expf(s_s[warp][hh][n] - mh[hh]) * ih[hh];
        arow[s_idx[warp][n]] = ps * 0.125f;
    }
}

// ---------------- launch ----------------
extern "C" void kernel_launch(void* const* d_in, const int* in_sizes, int n_in,
                              void* d_out, int out_size) {
    const float* x  = (const float*)d_in[0];
    const int* edges = (const int*)d_in[1];
    const float* Wq = (const float*)d_in[2];
    const float* bq = (const float*)d_in[3];
    const float* Wk = (const float*)d_in[4];
    const float* bk = (const float*)d_in[5];
    const float* Wv = (const float*)d_in[6];
    const float* bv = (const float*)d_in[7];
    const float* Wo = (const float*)d_in[8];
    const float* bo = (const float*)d_in[9];
    const float* temp = (const float*)d_in[10];

    float* out = (float*)d_out;
    float* attn_out = out + (size_t)BB * NNODES * DD;

    void* maskp = nullptr;
    cudaGetSymbolAddress(&maskp, g_mask);

    cudaMemsetAsync(attn_out, 0, (size_t)BB * NNODES * NNODES * sizeof(float), 0);
    cudaMemsetAsync(maskp, 0, (size_t)NNODES * MASK_WORDS * sizeof(unsigned int), 0);

    build_mask_kernel<<<(EE + NNODES + 255) / 256, 256>>>(edges);

    dim3 gqkv(BB * NNODES / 64, DD / 128, 3);
    qkv_kernel<<<gqkv, 128>>>(x, Wq, bq, Wk, bk, Wv, bv);

    attn_kernel<<<BB * NNODES / WPB, 32 * WPB>>>(temp, attn_out);

    dim3 go(BB * NNODES / 64, DD / 128, 1);
    oproj_kernel<<<go, 128>>>(Wo, bo, out);
}

// round 13
// speedup vs baseline: 1.1063x; 1.1063x over previous
#include <cuda_runtime.h>
#include <cstdint>

#define BB 4
#define NNODES 2048
#define DD 256
#define HH 8
#define HDIM 32
#define EE 65536
#define MASK_WORDS (NNODES / 32)   /* 64 */
#define MAXDEG 128
#define WPB 8                      /* warps per block in attn */

// ---------------- device scratch (no allocation allowed) ----------------
__device__ float g_Q[BB * NNODES * DD];
__device__ float g_K[BB * NNODES * DD];
__device__ float g_V[BB * NNODES * DD];
__device__ float g_att[BB * NNODES * DD];
__device__ unsigned int g_mask[NNODES * MASK_WORDS];

// ---------------- packed f32x2 helpers ----------------
#define FMA2(d, a, b, c) \
    asm("fma.rn.f32x2 %0, %1, %2, %3;" : "=l"(d) : "l"(a), "l"(b), "l"(c))
#define PACK_DUP(d, x) \
    asm("mov.b64 %0, {%1, %1};" : "=l"(d) : "r"(__float_as_uint(x)))
#define UNPACK2(lo, hi, v) \
    asm("mov.b64 {%0, %1}, %2;" : "=f"(lo), "=f"(hi) : "l"(v))

// ---------------- adjacency mask ----------------
__global__ void build_mask_kernel(const int* __restrict__ edges) {
    int idx = blockIdx.x * blockDim.x + threadIdx.x;
    if (idx < EE) {
        int s = edges[idx];
        int d = edges[EE + idx];
        atomicOr(&g_mask[s * MASK_WORDS + (d >> 5)], 1u << (d & 31));
        atomicOr(&g_mask[d * MASK_WORDS + (s >> 5)], 1u << (s & 31));
    } else if (idx < EE + NNODES) {
        int i = idx - EE;
        atomicOr(&g_mask[i * MASK_WORDS + (i >> 5)], 1u << (i & 31));
    }
}

// ---------------- SGEMM: C[M,256] = A[M,256] @ W[256,256]^T + bias ----------------
// 128 threads, BM=64, BN=64, BK=16. Per-thread micro-tile 8(M)x4(N) computed
// with packed fma.rn.f32x2 (FFMA2): M handled as 4 packed pairs.
__device__ __forceinline__ void sgemm_body(const float* __restrict__ A,
                                           const float* __restrict__ W,
                                           const float* __restrict__ bias,
                                           float* __restrict__ C) {
    __shared__ float As[16][64];
    __shared__ float Ws[16][64];

    const int tid = threadIdx.x;          // 0..127
    const int m0 = blockIdx.x * 64;
    const int n0 = blockIdx.y * 64;
    const int tx = tid & 15;              // 0..15 -> N offset tx*4
    const int ty = tid >> 4;              // 0..7  -> M offset ty*8
    const int lr = tid >> 1;              // load row 0..63
    const int lh = (tid & 1) * 8;         // k-half offset 0 or 8

    // acc[j][p] = packed pair of C rows (m0+ty*8+2p, +2p+1), col n0+tx*4+j
    unsigned long long acc[4][4];
#pragma unroll
    for (int j = 0; j < 4; j++)
#pragma unroll
        for (int p = 0; p < 4; p++) acc[j][p] = 0ull;

    const float* Ap = A + (size_t)(m0 + lr) * 256 + lh;
    const float* Wp = W + (size_t)(n0 + lr) * 256 + lh;

    for (int k0 = 0; k0 < 256; k0 += 16) {
        float4 a0 = reinterpret_cast<const float4*>(Ap + k0)[0];
        float4 a1 = reinterpret_cast<const float4*>(Ap + k0)[1];
        float4 w0 = reinterpret_cast<const float4*>(Wp + k0)[0];
        float4 w1 = reinterpret_cast<const float4*>(Wp + k0)[1];

        __syncthreads();   // previous iteration's readers done
        As[lh + 0][lr] = a0.x; As[lh + 1][lr] = a0.y; As[lh + 2][lr] = a0.z; As[lh + 3][lr] = a0.w;
        As[lh + 4][lr] = a1.x; As[lh + 5][lr] = a1.y; As[lh + 6][lr] = a1.z; As[lh + 7][lr] = a1.w;
        Ws[lh + 0][lr] = w0.x; Ws[lh + 1][lr] = w0.y; Ws[lh + 2][lr] = w0.z; Ws[lh + 3][lr] = w0.w;
        Ws[lh + 4][lr] = w1.x; Ws[lh + 5][lr] = w1.y; Ws[lh + 6][lr] = w1.z; Ws[lh + 7][lr] = w1.w;
        __syncthreads();

#pragma unroll
        for (int k = 0; k < 16; k++) {
            // A: 8 floats = 4 packed M-pairs (b64 pairs straight out of LDS.128)
            ulonglong2 aP0 = *reinterpret_cast<const ulonglong2*>(&As[k][ty * 8]);
            ulonglong2 aP1 = *reinterpret_cast<const ulonglong2*>(&As[k][ty * 8 + 4]);
            float4 wv = *reinterpret_cast<const float4*>(&Ws[k][tx * 4]);
            unsigned long long wd0, wd1, wd2, wd3;
            PACK_DUP(wd0, wv.x);
            PACK_DUP(wd1, wv.y);
            PACK_DUP(wd2, wv.z);
            PACK_DUP(wd3, wv.w);
            FMA2(acc[0][0], aP0.x, wd0, acc[0][0]);
            FMA2(acc[0][1], aP0.y, wd0, acc[0][1]);
            FMA2(acc[0][2], aP1.x, wd0, acc[0][2]);
            FMA2(acc[0][3], aP1.y, wd0, acc[0][3]);
            FMA2(acc[1][0], aP0.x, wd1, acc[1][0]);
            FMA2(acc[1][1], aP0.y, wd1, acc[1][1]);
            FMA2(acc[1][2], aP1.x, wd1, acc[1][2]);
            FMA2(acc[1][3], aP1.y, wd1, acc[1][3]);
            FMA2(acc[2][0], aP0.x, wd2, acc[2][0]);
            FMA2(acc[2][1], aP0.y, wd2, acc[2][1]);
            FMA2(acc[2][2], aP1.x, wd2, acc[2][2]);
            FMA2(acc[2][3], aP1.y, wd2, acc[2][3]);
            FMA2(acc[3][0], aP0.x, wd3, acc[3][0]);
            FMA2(acc[3][1], aP0.y, wd3, acc[3][1]);
            FMA2(acc[3][2], aP1.x, wd3, acc[3][2]);
            FMA2(acc[3][3], aP1.y, wd3, acc[3][3]);
        }
    }

    float bs[4];
#pragma unroll
    for (int j = 0; j < 4; j++) bs[j] = bias[n0 + tx * 4 + j];

    // unpack: rows m0+ty*8+2p(+1), cols n0+tx*4..+3 -> float4 stores
#pragma unroll
    for (int p = 0; p < 4; p++) {
        float lo0, hi0, lo1, hi1, lo2, hi2, lo3, hi3;
        UNPACK2(lo0, hi0, acc[0][p]);
        UNPACK2(lo1, hi1, acc[1][p]);
        UNPACK2(lo2, hi2, acc[2][p]);
        UNPACK2(lo3, hi3, acc[3][p]);
        float4 r0, r1;
        r0.x = lo0 + bs[0]; r0.y = lo1 + bs[1]; r0.z = lo2 + bs[2]; r0.w = lo3 + bs[3];
        r1.x = hi0 + bs[0]; r1.y = hi1 + bs[1]; r1.z = hi2 + bs[2]; r1.w = hi3 + bs[3];
        float* C0 = C + (size_t)(m0 + ty * 8 + 2 * p) * 256 + n0 + tx * 4;
        float* C1 = C0 + 256;
        *reinterpret_cast<float4*>(C0) = r0;
        *reinterpret_cast<float4*>(C1) = r1;
    }
}

__global__ void __launch_bounds__(128) qkv_kernel(const float* __restrict__ x,
                                                  const float* __restrict__ Wq, const float* __restrict__ bq,
                                                  const float* __restrict__ Wk, const float* __restrict__ bk,
                                                  const float* __restrict__ Wv, const float* __restrict__ bv) {
    const float* W; const float* bb; float* C;
    if (blockIdx.z == 0)      { W = Wq; bb = bq; C = g_Q; }
    else if (blockIdx.z == 1) { W = Wk; bb = bk; C = g_K; }
    else                      { W = Wv; bb = bv; C = g_V; }
    sgemm_body(x, W, bb, C);
}

__global__ void __launch_bounds__(128) oproj_kernel(const float* __restrict__ Wo,
                                                    const float* __restrict__ bo,
                                                    float* __restrict__ out) {
    sgemm_body(g_att, Wo, bo, out);
}

// ---------------- sparse masked attention: single pass, online softmax ----------------
__global__ void __launch_bounds__(32 * WPB) attn_kernel(const float* __restrict__ tptr,
                                                        float* __restrict__ attn_out) {
    __shared__ unsigned short s_idx[WPB][MAXDEG];
    __shared__ float s_s[WPB][8][MAXDEG + 1];   // raw scaled scores, +1 pad
    __shared__ float s_ml[WPB][8][2];           // per-head {max, 1/l}

    const int warp = threadIdx.x >> 5;
    const int lane = threadIdx.x & 31;
    const int flat = blockIdx.x * WPB + warp;        // 0 .. B*N-1
    const int b = flat >> 11;
    const int i = flat & (NNODES - 1);
    const float invT = 1.0f / (*tptr);

    // --- enumerate neighbors from bitmask row i ---
    unsigned int w0 = g_mask[i * MASK_WORDS + lane];
    unsigned int w1 = g_mask[i * MASK_WORDS + 32 + lane];
    int c0 = __popc(w0), c1 = __popc(w1);

    int incl0 = c0;
#pragma unroll
    for (int d = 1; d < 32; d <<= 1) {
        int t = __shfl_up_sync(0xffffffffu, incl0, d);
        if (lane >= d) incl0 += t;
    }
    int tot0 = __shfl_sync(0xffffffffu, incl0, 31);
    int off0 = incl0 - c0;

    int incl1 = c1;
#pragma unroll
    for (int d = 1; d < 32; d <<= 1) {
        int t = __shfl_up_sync(0xffffffffu, incl1, d);
        if (lane >= d) incl1 += t;
    }
    int tot1 = __shfl_sync(0xffffffffu, incl1, 31);
    int off1 = tot0 + incl1 - c1;

    int deg = tot0 + tot1;
    if (deg > MAXDEG) deg = MAXDEG;   // statistically unreachable (Poisson(64) tail)

    {
        int o = off0, base = lane * 32;
        while (w0) {
            int p = __ffs(w0) - 1; w0 &= w0 - 1;
            if (o < MAXDEG) s_idx[warp][o] = (unsigned short)(base + p);
            o++;
        }
        o = off1; base = 1024 + lane * 32;
        while (w1) {
            int p = __ffs(w1) - 1; w1 &= w1 - 1;
            if (o < MAXDEG) s_idx[warp][o] = (unsigned short)(base + p);
            o++;
        }
    }
    __syncwarp();

    const int h = lane >> 2;          // head owned by this 4-lane group
    const int s = lane & 3;
    const size_t rowbase = (size_t)(b * NNODES + i) * DD;
    const float* __restrict__ Kb = g_K + (size_t)b * NNODES * DD;
    const float* __restrict__ Vb = g_V + (size_t)b * NNODES * DD;

    const float* Qrow = g_Q + rowbase + h * 32 + s * 8;
    const float4 qa = reinterpret_cast<const float4*>(Qrow)[0];
    const float4 qb = reinterpret_cast<const float4*>(Qrow)[1];

    float m = -1e30f, l = 0.f;
    float4 acca = {0.f, 0.f, 0.f, 0.f};
    float4 accb = {0.f, 0.f, 0.f, 0.f};

    for (int nb = 0; nb < deg; nb += 2) {
        const bool has1 = (nb + 1) < deg;
        const int j0 = s_idx[warp][nb];
        const int j1 = s_idx[warp][has1 ? nb + 1 : nb];

        const float* K0 = Kb + (size_t)j0 * DD + h * 32 + s * 8;
        const float* K1 = Kb + (size_t)j1 * DD + h * 32 + s * 8;
        const float* V0 = Vb + (size_t)j0 * DD + lane * 8;
        const float* V1 = Vb + (size_t)j1 * DD + lane * 8;
        float4 ka0 = reinterpret_cast<const float4*>(K0)[0];
        float4 kb0 = reinterpret_cast<const float4*>(K0)[1];
        float4 ka1 = reinterpret_cast<const float4*>(K1)[0];
        float4 kb1 = reinterpret_cast<const float4*>(K1)[1];
        float4 va0 = reinterpret_cast<const float4*>(V0)[0];
        float4 vb0 = reinterpret_cast<const float4*>(V0)[1];
        float4 va1 = reinterpret_cast<const float4*>(V1)[0];
        float4 vb1 = reinterpret_cast<const float4*>(V1)[1];

        float d0 = qa.x * ka0.x + qa.y * ka0.y + qa.z * ka0.z + qa.w * ka0.w
                 + qb.x * kb0.x + qb.y * kb0.y + qb.z * kb0.z + qb.w * kb0.w;
        float d1 = qa.x * ka1.x + qa.y * ka1.y + qa.z * ka1.z + qa.w * ka1.w
                 + qb.x * kb1.x + qb.y * kb1.y + qb.z * kb1.z + qb.w * kb1.w;
        d0 += __shfl_xor_sync(0xffffffffu, d0, 1);
        d0 += __shfl_xor_sync(0xffffffffu, d0, 2);
        d1 += __shfl_xor_sync(0xffffffffu, d1, 1);
        d1 += __shfl_xor_sync(0xffffffffu, d1, 2);

        const float s0 = d0 * invT;
        const float s1 = has1 ? d1 * invT : -1e30f;
        if (s == 0) {
            s_s[warp][h][nb] = s0;
            if (has1) s_s[warp][h][nb + 1] = s1;
        }

        const float mn = fmaxf(m, fmaxf(s0, s1));
        const float c  = __expf(m - mn);
        const float e0 = __expf(s0 - mn);
        const float e1 = __expf(s1 - mn);
        l = l * c + e0 + e1;
        acca.x = acca.x * c + e0 * va0.x + e1 * va1.x;
        acca.y = acca.y * c + e0 * va0.y + e1 * va1.y;
        acca.z = acca.z * c + e0 * va0.z + e1 * va1.z;
        acca.w = acca.w * c + e0 * va0.w + e1 * va1.w;
        accb.x = accb.x * c + e0 * vb0.x + e1 * vb1.x;
        accb.y = accb.y * c + e0 * vb0.y + e1 * vb1.y;
        accb.z = accb.z * c + e0 * vb0.z + e1 * vb1.z;
        accb.w = accb.w * c + e0 * vb0.w + e1 * vb1.w;
        m = mn;
    }

    const float invl = 1.0f / l;
    if (s == 0) {
        s_ml[warp][h][0] = m;
        s_ml[warp][h][1] = invl;
    }

    // --- attended output (normalize) ---
    acca.x *= invl; acca.y *= invl; acca.z *= invl; acca.w *= invl;
    accb.x *= invl; accb.y *= invl; accb.z *= invl; accb.w *= invl;
    float* Ao = g_att + rowbase + lane * 8;
    reinterpret_cast<float4*>(Ao)[0] = acca;
    reinterpret_cast<float4*>(Ao)[1] = accb;

    __syncwarp();

    // --- attn_mean sparse scatter: lanes parallel over neighbors ---
    float mh[8], ih[8];
#pragma unroll
    for (int hh = 0; hh < 8; hh++) {
        mh[hh] = s_ml[warp][hh][0];
        ih[hh] = s_ml[warp][hh][1];
    }
    float* arow = attn_out + ((size_t)b * NNODES + i) * NNODES;
    for (int n = lane; n < deg; n += 32) {
        float ps = 0.f;
#pragma unroll
        for (int hh = 0; hh < 8; hh++)
            ps += __expf(s_s[warp][hh][n] - mh[hh]) * ih[hh];
        arow[s_idx[warp][n]] = ps * 0.125f;
    }
}

// ---------------- launch ----------------
extern "C" void kernel_launch(void* const* d_in, const int* in_sizes, int n_in,
                              void* d_out, int out_size) {
    const float* x  = (const float*)d_in[0];
    const int* edges = (const int*)d_in[1];
    const float* Wq = (const float*)d_in[2];
    const float* bq = (const float*)d_in[3];
    const float* Wk = (const float*)d_in[4];
    const float* bk = (const float*)d_in[5];
    const float* Wv = (const float*)d_in[6];
    const float* bv = (const float*)d_in[7];
    const float* Wo = (const float*)d_in[8];
    const float* bo = (const float*)d_in[9];
    const float* temp = (const float*)d_in[10];

    float* out = (float*)d_out;
    float* attn_out = out + (size_t)BB * NNODES * DD;

    void* maskp = nullptr;
    cudaGetSymbolAddress(&maskp, g_mask);

    cudaMemsetAsync(attn_out, 0, (size_t)BB * NNODES * NNODES * sizeof(float), 0);
    cudaMemsetAsync(maskp, 0, (size_t)NNODES * MASK_WORDS * sizeof(unsigned int), 0);

    build_mask_kernel<<<(EE + NNODES + 255) / 256, 256>>>(edges);

    dim3 gqkv(BB * NNODES / 64, DD / 64, 3);
    qkv_kernel<<<gqkv, 128>>>(x, Wq, bq, Wk, bk, Wv, bv);

    attn_kernel<<<BB * NNODES / WPB, 32 * WPB>>>(temp, attn_out);

    dim3 go(BB * NNODES / 64, DD / 64, 1);
    oproj_kernel<<<go, 128>>>(Wo, bo, out);
}

// round 14
// speedup vs baseline: 1.1168x; 1.0095x over previous
#include <cuda_runtime.h>
#include <cstdint>

#define BB 4
#define NNODES 2048
#define DD 256
#define HH 8
#define HDIM 32
#define EE 65536
#define MASK_WORDS (NNODES / 32)   /* 64 */
#define MAXDEG 128
#define WPB 8                      /* warps per block in attn */

#define BM 128
#define BN 64
#define BK 16
#define APAD 136                   /* BM + 8 : conflict-free frag LDS */
#define WPAD2 72                   /* BN + 8 */

// ---------------- device scratch (no allocation allowed) ----------------
__device__ float g_Q[BB * NNODES * DD];
__device__ float g_K[BB * NNODES * DD];
__device__ float g_V[BB * NNODES * DD];
__device__ float g_att[BB * NNODES * DD];
__device__ unsigned int g_mask[NNODES * MASK_WORDS];

// ---------------- tf32 helpers ----------------
__device__ __forceinline__ unsigned f2tf(float x) {
    unsigned r;
    asm("cvt.rna.tf32.f32 %0, %1;" : "=r"(r) : "f"(x));
    return r;
}

__device__ __forceinline__ void mma8(float* d,
                                     unsigned a0, unsigned a1, unsigned a2, unsigned a3,
                                     unsigned b0, unsigned b1) {
    asm("mma.sync.aligned.m16n8k8.row.col.f32.tf32.tf32.f32 "
        "{%0,%1,%2,%3},{%4,%5,%6,%7},{%8,%9},{%0,%1,%2,%3};"
        : "+f"(d[0]), "+f"(d[1]), "+f"(d[2]), "+f"(d[3])
        : "r"(a0), "r"(a1), "r"(a2), "r"(a3), "r"(b0), "r"(b1));
}

// ---------------- adjacency mask ----------------
__global__ void build_mask_kernel(const int* __restrict__ edges) {
    int idx = blockIdx.x * blockDim.x + threadIdx.x;
    if (idx < EE) {
        int s = edges[idx];
        int d = edges[EE + idx];
        atomicOr(&g_mask[s * MASK_WORDS + (d >> 5)], 1u << (d & 31));
        atomicOr(&g_mask[d * MASK_WORDS + (s >> 5)], 1u << (s & 31));
    } else if (idx < EE + NNODES) {
        int i = idx - EE;
        atomicOr(&g_mask[i * MASK_WORDS + (i >> 5)], 1u << (i & 31));
    }
}

// ---------------- tensor-core GEMM: C[M,256] = A[M,256] @ W[256,256]^T + bias ----
// 256 threads (8 warps), BM=128, BN=64, BK=16. Warp tile 32x32 = 2x4 m16n8k8.
// 3xTF32: A,W split into tf32 hi/lo during smem store; 3 mma per tile per k-step
// (hi*hi + lo*hi + hi*lo) all into one fp32 accumulator -> ~2e-7 rel error.
__device__ __forceinline__ void gemm_tc_body(const float* __restrict__ A,
                                             const float* __restrict__ W,
                                             const float* __restrict__ bias,
                                             float* __restrict__ C) {
    __shared__ float Ah[BK][APAD];
    __shared__ float Al[BK][APAD];
    __shared__ float Wh[BK][WPAD2];
    __shared__ float Wl[BK][WPAD2];

    const int tid = threadIdx.x;            // 0..255
    const int warp = tid >> 5;
    const int lane = tid & 31;
    const int wm = warp & 3;                // 0..3  M-warp
    const int wn = warp >> 2;               // 0..1  N-warp
    const int g = lane >> 2;                // groupID 0..7
    const int t = lane & 3;                 // threadID-in-group 0..3

    const int mrow = tid >> 2;              // 0..63  (load row)
    const int kq = (tid & 3) * 4;           // 0,4,8,12

    float acc[2][4][4];
#pragma unroll
    for (int i = 0; i < 2; i++)
#pragma unroll
        for (int j = 0; j < 4; j++)
#pragma unroll
            for (int r = 0; r < 4; r++) acc[i][j][r] = 0.f;

    const float* Abase = A + (size_t)(blockIdx.x * BM) * 256;
    const float* Wbase = W + (size_t)(blockIdx.y * BN) * 256;

    for (int k0 = 0; k0 < 256; k0 += BK) {
        float4 av0 = *reinterpret_cast<const float4*>(Abase + (size_t)mrow * 256 + k0 + kq);
        float4 av1 = *reinterpret_cast<const float4*>(Abase + (size_t)(mrow + 64) * 256 + k0 + kq);
        float4 wv  = *reinterpret_cast<const float4*>(Wbase + (size_t)mrow * 256 + k0 + kq);

        __syncthreads();   // previous iteration's readers done
#pragma unroll
        for (int j = 0; j < 4; j++) {
            float v0 = (&av0.x)[j];
            unsigned h0 = f2tf(v0); float hf0 = __uint_as_float(h0);
            Ah[kq + j][mrow] = hf0;
            Al[kq + j][mrow] = __uint_as_float(f2tf(v0 - hf0));
            float v1 = (&av1.x)[j];
            unsigned h1 = f2tf(v1); float hf1 = __uint_as_float(h1);
            Ah[kq + j][mrow + 64] = hf1;
            Al[kq + j][mrow + 64] = __uint_as_float(f2tf(v1 - hf1));
            float vw = (&wv.x)[j];
            unsigned hw = f2tf(vw); float hfw = __uint_as_float(hw);
            Wh[kq + j][mrow] = hfw;
            Wl[kq + j][mrow] = __uint_as_float(f2tf(vw - hfw));
        }
        __syncthreads();

#pragma unroll
        for (int kk = 0; kk < 2; kk++) {
            const int kb = kk * 8;
            unsigned ah[2][4], al[2][4], bh[4][2], bl[4][2];
#pragma unroll
            for (int i = 0; i < 2; i++) {
                const int mb = wm * 32 + i * 16;
                ah[i][0] = __float_as_uint(Ah[kb + t][mb + g]);
                ah[i][1] = __float_as_uint(Ah[kb + t][mb + g + 8]);
                ah[i][2] = __float_as_uint(Ah[kb + t + 4][mb + g]);
                ah[i][3] = __float_as_uint(Ah[kb + t + 4][mb + g + 8]);
                al[i][0] = __float_as_uint(Al[kb + t][mb + g]);
                al[i][1] = __float_as_uint(Al[kb + t][mb + g + 8]);
                al[i][2] = __float_as_uint(Al[kb + t + 4][mb + g]);
                al[i][3] = __float_as_uint(Al[kb + t + 4][mb + g + 8]);
            }
#pragma unroll
            for (int j = 0; j < 4; j++) {
                const int nb = wn * 32 + j * 8 + g;
                bh[j][0] = __float_as_uint(Wh[kb + t][nb]);
                bh[j][1] = __float_as_uint(Wh[kb + t + 4][nb]);
                bl[j][0] = __float_as_uint(Wl[kb + t][nb]);
                bl[j][1] = __float_as_uint(Wl[kb + t + 4][nb]);
            }
#pragma unroll
            for (int i = 0; i < 2; i++)
#pragma unroll
                for (int j = 0; j < 4; j++) {
                    mma8(acc[i][j], ah[i][0], ah[i][1], ah[i][2], ah[i][3], bh[j][0], bh[j][1]);
                    mma8(acc[i][j], al[i][0], al[i][1], al[i][2], al[i][3], bh[j][0], bh[j][1]);
                    mma8(acc[i][j], ah[i][0], ah[i][1], ah[i][2], ah[i][3], bl[j][0], bl[j][1]);
                }
        }
    }

    // epilogue: c0,c1 -> row g, cols 2t,2t+1 ; c2,c3 -> row g+8
#pragma unroll
    for (int i = 0; i < 2; i++) {
        const int row0 = blockIdx.x * BM + wm * 32 + i * 16 + g;
#pragma unroll
        for (int j = 0; j < 4; j++) {
            const int col = blockIdx.y * BN + wn * 32 + j * 8 + t * 2;
            const float b0 = bias[col], b1 = bias[col + 1];
            float2 r0 = {acc[i][j][0] + b0, acc[i][j][1] + b1};
            float2 r1 = {acc[i][j][2] + b0, acc[i][j][3] + b1};
            *reinterpret_cast<float2*>(C + (size_t)row0 * 256 + col) = r0;
            *reinterpret_cast<float2*>(C + (size_t)(row0 + 8) * 256 + col) = r1;
        }
    }
}

__global__ void __launch_bounds__(256) qkv_kernel(const float* __restrict__ x,
                                                  const float* __restrict__ Wq, const float* __restrict__ bq,
                                                  const float* __restrict__ Wk, const float* __restrict__ bk,
                                                  const float* __restrict__ Wv, const float* __restrict__ bv) {
    const float* W; const float* bb; float* C;
    if (blockIdx.z == 0)      { W = Wq; bb = bq; C = g_Q; }
    else if (blockIdx.z == 1) { W = Wk; bb = bk; C = g_K; }
    else                      { W = Wv; bb = bv; C = g_V; }
    gemm_tc_body(x, W, bb, C);
}

__global__ void __launch_bounds__(256) oproj_kernel(const float* __restrict__ Wo,
                                                    const float* __restrict__ bo,
                                                    float* __restrict__ out) {
    gemm_tc_body(g_att, Wo, bo, out);
}

// ---------------- sparse masked attention: single pass, online softmax ----------------
__global__ void __launch_bounds__(32 * WPB) attn_kernel(const float* __restrict__ tptr,
                                                        float* __restrict__ attn_out) {
    __shared__ unsigned short s_idx[WPB][MAXDEG];
    __shared__ float s_s[WPB][8][MAXDEG + 1];   // raw scaled scores, +1 pad
    __shared__ float s_ml[WPB][8][2];           // per-head {max, 1/l}

    const int warp = threadIdx.x >> 5;
    const int lane = threadIdx.x & 31;
    const int flat = blockIdx.x * WPB + warp;        // 0 .. B*N-1
    const int b = flat >> 11;
    const int i = flat & (NNODES - 1);
    const float invT = 1.0f / (*tptr);

    // --- enumerate neighbors from bitmask row i ---
    unsigned int w0 = g_mask[i * MASK_WORDS + lane];
    unsigned int w1 = g_mask[i * MASK_WORDS + 32 + lane];
    int c0 = __popc(w0), c1 = __popc(w1);

    int incl0 = c0;
#pragma unroll
    for (int d = 1; d < 32; d <<= 1) {
        int t = __shfl_up_sync(0xffffffffu, incl0, d);
        if (lane >= d) incl0 += t;
    }
    int tot0 = __shfl_sync(0xffffffffu, incl0, 31);
    int off0 = incl0 - c0;

    int incl1 = c1;
#pragma unroll
    for (int d = 1; d < 32; d <<= 1) {
        int t = __shfl_up_sync(0xffffffffu, incl1, d);
        if (lane >= d) incl1 += t;
    }
    int tot1 = __shfl_sync(0xffffffffu, incl1, 31);
    int off1 = tot0 + incl1 - c1;

    int deg = tot0 + tot1;
    if (deg > MAXDEG) deg = MAXDEG;   // statistically unreachable (Poisson(64) tail)

    {
        int o = off0, base = lane * 32;
        while (w0) {
            int p = __ffs(w0) - 1; w0 &= w0 - 1;
            if (o < MAXDEG) s_idx[warp][o] = (unsigned short)(base + p);
            o++;
        }
        o = off1; base = 1024 + lane * 32;
        while (w1) {
            int p = __ffs(w1) - 1; w1 &= w1 - 1;
            if (o < MAXDEG) s_idx[warp][o] = (unsigned short)(base + p);
            o++;
        }
    }
    __syncwarp();

    const int h = lane >> 2;          // head owned by this 4-lane group
    const int s = lane & 3;
    const size_t rowbase = (size_t)(b * NNODES + i) * DD;
    const float* __restrict__ Kb = g_K + (size_t)b * NNODES * DD;
    const float* __restrict__ Vb = g_V + (size_t)b * NNODES * DD;

    const float* Qrow = g_Q + rowbase + h * 32 + s * 8;
    const float4 qa = reinterpret_cast<const float4*>(Qrow)[0];
    const float4 qb = reinterpret_cast<const float4*>(Qrow)[1];

    float m = -1e30f, l = 0.f;
    float4 acca = {0.f, 0.f, 0.f, 0.f};
    float4 accb = {0.f, 0.f, 0.f, 0.f};

    for (int nb = 0; nb < deg; nb += 2) {
        const bool has1 = (nb + 1) < deg;
        const int j0 = s_idx[warp][nb];
        const int j1 = s_idx[warp][has1 ? nb + 1 : nb];

        const float* K0 = Kb + (size_t)j0 * DD + h * 32 + s * 8;
        const float* K1 = Kb + (size_t)j1 * DD + h * 32 + s * 8;
        const float* V0 = Vb + (size_t)j0 * DD + lane * 8;
        const float* V1 = Vb + (size_t)j1 * DD + lane * 8;
        float4 ka0 = reinterpret_cast<const float4*>(K0)[0];
        float4 kb0 = reinterpret_cast<const float4*>(K0)[1];
        float4 ka1 = reinterpret_cast<const float4*>(K1)[0];
        float4 kb1 = reinterpret_cast<const float4*>(K1)[1];
        float4 va0 = reinterpret_cast<const float4*>(V0)[0];
        float4 vb0 = reinterpret_cast<const float4*>(V0)[1];
        float4 va1 = reinterpret_cast<const float4*>(V1)[0];
        float4 vb1 = reinterpret_cast<const float4*>(V1)[1];

        float d0 = qa.x * ka0.x + qa.y * ka0.y + qa.z * ka0.z + qa.w * ka0.w
                 + qb.x * kb0.x + qb.y * kb0.y + qb.z * kb0.z + qb.w * kb0.w;
        float d1 = qa.x * ka1.x + qa.y * ka1.y + qa.z * ka1.z + qa.w * ka1.w
                 + qb.x * kb1.x + qb.y * kb1.y + qb.z * kb1.z + qb.w * kb1.w;
        d0 += __shfl_xor_sync(0xffffffffu, d0, 1);
        d0 += __shfl_xor_sync(0xffffffffu, d0, 2);
        d1 += __shfl_xor_sync(0xffffffffu, d1, 1);
        d1 += __shfl_xor_sync(0xffffffffu, d1, 2);

        const float s0 = d0 * invT;
        const float s1 = has1 ? d1 * invT : -1e30f;
        if (s == 0) {
            s_s[warp][h][nb] = s0;
            if (has1) s_s[warp][h][nb + 1] = s1;
        }

        const float mn = fmaxf(m, fmaxf(s0, s1));
        const float c  = __expf(m - mn);
        const float e0 = __expf(s0 - mn);
        const float e1 = __expf(s1 - mn);
        l = l * c + e0 + e1;
        acca.x = acca.x * c + e0 * va0.x + e1 * va1.x;
        acca.y = acca.y * c + e0 * va0.y + e1 * va1.y;
        acca.z = acca.z * c + e0 * va0.z + e1 * va1.z;
        acca.w = acca.w * c + e0 * va0.w + e1 * va1.w;
        accb.x = accb.x * c + e0 * vb0.x + e1 * vb1.x;
        accb.y = accb.y * c + e0 * vb0.y + e1 * vb1.y;
        accb.z = accb.z * c + e0 * vb0.z + e1 * vb1.z;
        accb.w = accb.w * c + e0 * vb0.w + e1 * vb1.w;
        m = mn;
    }

    const float invl = 1.0f / l;
    if (s == 0) {
        s_ml[warp][h][0] = m;
        s_ml[warp][h][1] = invl;
    }

    // --- attended output (normalize) ---
    acca.x *= invl; acca.y *= invl; acca.z *= invl; acca.w *= invl;
    accb.x *= invl; accb.y *= invl; accb.z *= invl; accb.w *= invl;
    float* Ao = g_att + rowbase + lane * 8;
    reinterpret_cast<float4*>(Ao)[0] = acca;
    reinterpret_cast<float4*>(Ao)[1] = accb;

    __syncwarp();

    // --- attn_mean sparse scatter: lanes parallel over neighbors ---
    float mh[8], ih[8];
#pragma unroll
    for (int hh = 0; hh < 8; hh++) {
        mh[hh] = s_ml[warp][hh][0];
        ih[hh] = s_ml[warp][hh][1];
    }
    float* arow = attn_out + ((size_t)b * NNODES + i) * NNODES;
    for (int n = lane; n < deg; n += 32) {
        float ps = 0.f;
#pragma unroll
        for (int hh = 0; hh < 8; hh++)
            ps += __expf(s_s[warp][hh][n] - mh[hh]) * ih[hh];
        arow[s_idx[warp][n]] = ps * 0.125f;
    }
}

// ---------------- launch ----------------
extern "C" void kernel_launch(void* const* d_in, const int* in_sizes, int n_in,
                              void* d_out, int out_size) {
    const float* x  = (const float*)d_in[0];
    const int* edges = (const int*)d_in[1];
    const float* Wq = (const float*)d_in[2];
    const float* bq = (const float*)d_in[3];
    const float* Wk = (const float*)d_in[4];
    const float* bk = (const float*)d_in[5];
    const float* Wv = (const float*)d_in[6];
    const float* bv = (const float*)d_in[7];
    const float* Wo = (const float*)d_in[8];
    const float* bo = (const float*)d_in[9];
    const float* temp = (const float*)d_in[10];

    float* out = (float*)d_out;
    float* attn_out = out + (size_t)BB * NNODES * DD;

    void* maskp = nullptr;
    cudaGetSymbolAddress(&maskp, g_mask);

    cudaMemsetAsync(attn_out, 0, (size_t)BB * NNODES * NNODES * sizeof(float), 0);
    cudaMemsetAsync(maskp, 0, (size_t)NNODES * MASK_WORDS * sizeof(unsigned int), 0);

    build_mask_kernel<<<(EE + NNODES + 255) / 256, 256>>>(edges);

    dim3 gqkv(BB * NNODES / BM, DD / BN, 3);
    qkv_kernel<<<gqkv, 256>>>(x, Wq, bq, Wk, bk, Wv, bv);

    attn_kernel<<<BB * NNODES / WPB, 32 * WPB>>>(temp, attn_out);

    dim3 go(BB * NNODES / BM, DD / BN, 1);
    oproj_kernel<<<go, 256>>>(Wo, bo, out);
}